// round 8
// baseline (speedup 1.0000x reference)
#include <cuda_runtime.h>

#define N_CELLS 776
#define N_ANCHORS 3
#define N_CH 7
#define CONF_THRESH 0.8f
#define NO_OBJECT 0.5f

#define TOTAL_FLOATS (N_CELLS * N_ANCHORS * N_CH)   // 16296
#define HALF_CELLS   (N_CELLS / 2)                  // 388
#define CHUNK_FLOATS (HALF_CELLS * N_ANCHORS * N_CH) // 8148 (divisible by 4)
#define CHUNK_VEC4   (CHUNK_FLOATS / 4)             // 2037

__device__ __forceinline__ float sqrt_approx(float x) {
    float y;
    asm("sqrt.approx.f32 %0, %1;" : "=f"(y) : "f"(x));
    return y;
}

// Per-cell loss from a 21-float smem row. IoU argmax is done division-free:
// iou_i > iou_j  <=>  inter_i * den_j > inter_j * den_i   (den > 0 always).
__device__ __forceinline__ float cell_loss(const float* __restrict__ c,
                                           float lx, float ly, float lw, float lh,
                                           float lc, float l5, float l6,
                                           float area_b, float sqlx, float sqly) {
    float v[N_ANCHORS * N_CH];
    #pragma unroll
    for (int i = 0; i < N_ANCHORS * N_CH; i++) v[i] = c[i];

    float inter[N_ANCHORS], den[N_ANCHORS];
    #pragma unroll
    for (int a = 0; a < N_ANCHORS; a++) {
        const float px = v[a * N_CH + 0];
        const float py = v[a * N_CH + 1];
        const float pw = v[a * N_CH + 2];
        const float ph = v[a * N_CH + 3];
        const float ax = fmaxf(px - pw * 0.5f, lx - lw * 0.5f);
        const float ay = fmaxf(py - ph * 0.5f, ly - lh * 0.5f);
        const float bx = fminf(px + pw * 0.5f, lx + lw * 0.5f);
        const float by = fminf(py + ph * 0.5f, ly + lh * 0.5f);
        const float in = fabsf(fmaxf(bx - ax, 0.0f) * fmaxf(by - ay, 0.0f));
        const float area_a = fabsf(pw * ph);
        inter[a] = in;
        den[a] = area_a + area_b - in;   // union area, strictly > 0
    }

    // Sequential argmax with strict > (first max wins, matching jnp.argmax),
    // via cross-multiplication to avoid divisions.
    int best = 0;
    if (inter[1] * den[0] > inter[0] * den[1]) best = 1;
    if (inter[2] * den[best] > inter[best] * den[2]) best = 2;

    const float b0 = v[best * N_CH + 0];
    const float b1 = v[best * N_CH + 1];
    const float b4 = v[best * N_CH + 4];
    const float b5 = v[best * N_CH + 5];
    const float b6 = v[best * N_CH + 6];

    const float dx = lx - b0;
    const float dy = ly - b1;
    const float xy_loss = dx * dx + dy * dy;

    // Reference uses label[0]/label[1] and best[:,0]/best[:,1] inside the
    // sqrt terms — replicated verbatim.
    const float swx = sqlx - sqrt_approx(b0);
    const float swy = sqly - sqrt_approx(b1);
    const float wh_loss = swx * swx + swy * swy;

    const bool has_obj = b4 > CONF_THRESH;
    float class_loss = 0.0f;
    if (has_obj) {
        const float d5 = l5 - b5;
        const float d6 = l6 - b6;
        class_loss = d5 * d5 + d6 * d6;
    }
    const float dc = lc - b4;
    const float conf_sq = dc * dc;
    const float conf_loss = has_obj ? conf_sq : NO_OBJECT * conf_sq;

    return xy_loss + wh_loss + class_loss + conf_loss;
}

__global__ __launch_bounds__(1024, 1)
void yolo_loss_kernel(const float* __restrict__ pred,
                      const float* __restrict__ label,
                      float* __restrict__ out) {
    __shared__ float sh[CHUNK_FLOATS];      // 32592 B, double-used for both halves
    __shared__ float warp_sums[32];

    const int tid = threadIdx.x;

    const float lx = __ldg(&label[0]);
    const float ly = __ldg(&label[1]);
    const float lw = __ldg(&label[2]);
    const float lh = __ldg(&label[3]);
    const float lc = __ldg(&label[4]);
    const float l5 = __ldg(&label[5]);
    const float l6 = __ldg(&label[6]);
    const float area_b = fabsf(lw * lh);
    const float sqlx = sqrt_approx(lx);
    const float sqly = sqrt_approx(ly);

    const float4* __restrict__ pv = (const float4*)pred;
    float4* sv = (float4*)sh;

    float local = 0.0f;

    // ---- chunk 0: cells [0, 388) ----
    #pragma unroll
    for (int i = 0; i < 2; i++) {
        const int idx = tid + i * 1024;
        if (idx < CHUNK_VEC4) sv[idx] = pv[idx];
    }
    __syncthreads();
    if (tid < HALF_CELLS) {
        local = cell_loss(sh + tid * (N_ANCHORS * N_CH),
                          lx, ly, lw, lh, lc, l5, l6, area_b, sqlx, sqly);
    }
    __syncthreads();   // all chunk-0 reads done before overwrite

    // ---- chunk 1: cells [388, 776) ----
    #pragma unroll
    for (int i = 0; i < 2; i++) {
        const int idx = tid + i * 1024;
        if (idx < CHUNK_VEC4) sv[idx] = pv[CHUNK_VEC4 + idx];
    }
    __syncthreads();
    if (tid >= HALF_CELLS && tid < N_CELLS) {
        local = cell_loss(sh + (tid - HALF_CELLS) * (N_ANCHORS * N_CH),
                          lx, ly, lw, lh, lc, l5, l6, area_b, sqlx, sqly);
    }

    // ---- block reduction ----
    #pragma unroll
    for (int off = 16; off > 0; off >>= 1)
        local += __shfl_down_sync(0xFFFFFFFFu, local, off);

    const int lane = tid & 31;
    const int wid = tid >> 5;
    if (lane == 0) warp_sums[wid] = local;
    __syncthreads();

    if (wid == 0) {
        float s = warp_sums[lane];
        #pragma unroll
        for (int off = 16; off > 0; off >>= 1)
            s += __shfl_down_sync(0xFFFFFFFFu, s, off);
        if (lane == 0) out[0] = s;
    }
}

extern "C" void kernel_launch(void* const* d_in, const int* in_sizes, int n_in,
                              void* d_out, int out_size) {
    const float* pred  = (const float*)d_in[0];
    const float* label = (const float*)d_in[1];
    float* out = (float*)d_out;
    yolo_loss_kernel<<<1, 1024>>>(pred, label, out);
}

// round 10
// speedup vs baseline: 1.3413x; 1.3413x over previous
#include <cuda_runtime.h>

#define N_CELLS 776
#define N_ANCHORS 3
#define N_CH 7
#define CONF_THRESH 0.8f
#define NO_OBJECT 0.5f

#define CELL_F      (N_ANCHORS * N_CH)          // 21 floats/cell
#define TOTAL_F     (N_CELLS * CELL_F)          // 16296 floats
#define TOTAL_V4    (TOTAL_F / 4)               // 4074 float4 (16296 % 4 == 0)
#define CELLS_PER_CTA 32
#define N_CTAS      ((N_CELLS + CELLS_PER_CTA - 1) / CELLS_PER_CTA)  // 25
#define CTA_F       (CELLS_PER_CTA * CELL_F)    // 672 floats
#define CTA_V4      (CTA_F / 4)                 // 168 float4

// Cross-CTA reduction scratch. Zero-initialized at module load; the
// last-arriving CTA leaves counter wrapped to 0 for the next replay.
__device__ float        g_partials[N_CTAS];
__device__ unsigned int g_counter;

__device__ __forceinline__ float sqrt_approx(float x) {
    float y;
    asm("sqrt.approx.f32 %0, %1;" : "=f"(y) : "f"(x));
    return y;
}

__device__ __forceinline__ float ld_volatile(const float* p) {
    float v;
    asm volatile("ld.volatile.global.f32 %0, [%1];" : "=f"(v) : "l"(p));
    return v;
}

__global__ __launch_bounds__(32, 1)
void yolo_loss_kernel(const float* __restrict__ pred,
                      const float* __restrict__ label,
                      float* __restrict__ out) {
    __shared__ float sh[CTA_F];   // 2688 B: this CTA's 32 cells

    const int lane = threadIdx.x;
    const int bid  = blockIdx.x;

    // ---- stage this CTA's cells into smem (coalesced float4) ----
    {
        const float4* __restrict__ pv = (const float4*)pred;
        float4* sv = (float4*)sh;
        const int base = bid * CTA_V4;
        #pragma unroll
        for (int i = 0; i < 6; i++) {                 // 6*32 = 192 >= 168
            const int li = lane + i * 32;
            if (li < CTA_V4 && base + li < TOTAL_V4)
                sv[li] = pv[base + li];
        }
    }

    const float lx = __ldg(&label[0]);
    const float ly = __ldg(&label[1]);
    const float lw = __ldg(&label[2]);
    const float lh = __ldg(&label[3]);
    const float lc = __ldg(&label[4]);
    const float l5 = __ldg(&label[5]);
    const float l6 = __ldg(&label[6]);
    const float area_b = fabsf(lw * lh);
    const float sqlx = sqrt_approx(lx);
    const float sqly = sqrt_approx(ly);

    __syncwarp();

    // ---- per-cell loss ----
    float local = 0.0f;
    const int cell = bid * CELLS_PER_CTA + lane;
    if (cell < N_CELLS) {
        const float* c = sh + lane * CELL_F;   // stride 21 words: conflict-free

        float v[CELL_F];
        #pragma unroll
        for (int i = 0; i < CELL_F; i++) v[i] = c[i];

        float inter[N_ANCHORS], den[N_ANCHORS];
        #pragma unroll
        for (int a = 0; a < N_ANCHORS; a++) {
            const float px = v[a * N_CH + 0];
            const float py = v[a * N_CH + 1];
            const float pw = v[a * N_CH + 2];
            const float ph = v[a * N_CH + 3];
            const float ax = fmaxf(px - pw * 0.5f, lx - lw * 0.5f);
            const float ay = fmaxf(py - ph * 0.5f, ly - lh * 0.5f);
            const float bx = fminf(px + pw * 0.5f, lx + lw * 0.5f);
            const float by = fminf(py + ph * 0.5f, ly + lh * 0.5f);
            const float in = fabsf(fmaxf(bx - ax, 0.0f) * fmaxf(by - ay, 0.0f));
            inter[a] = in;
            den[a] = fabsf(pw * ph) + area_b - in;   // union area > 0
        }

        // Division-free argmax, strict > keeps first max (jnp.argmax).
        int best = 0;
        if (inter[1] * den[0] > inter[0] * den[1]) best = 1;
        if (inter[2] * den[best] > inter[best] * den[2]) best = 2;

        const float b0 = v[best * N_CH + 0];
        const float b1 = v[best * N_CH + 1];
        const float b4 = v[best * N_CH + 4];
        const float b5 = v[best * N_CH + 5];
        const float b6 = v[best * N_CH + 6];

        const float dx = lx - b0;
        const float dy = ly - b1;
        const float xy_loss = dx * dx + dy * dy;

        // Reference uses label[0]/label[1], best[:,0]/best[:,1] in the sqrt
        // terms — replicated verbatim.
        const float swx = sqlx - sqrt_approx(b0);
        const float swy = sqly - sqrt_approx(b1);
        const float wh_loss = swx * swx + swy * swy;

        const bool has_obj = b4 > CONF_THRESH;
        float class_loss = 0.0f;
        if (has_obj) {
            const float d5 = l5 - b5;
            const float d6 = l6 - b6;
            class_loss = d5 * d5 + d6 * d6;
        }
        const float dc = lc - b4;
        const float conf_sq = dc * dc;
        const float conf_loss = has_obj ? conf_sq : NO_OBJECT * conf_sq;

        local = xy_loss + wh_loss + class_loss + conf_loss;
    }

    // ---- warp reduce (fixed order -> deterministic) ----
    #pragma unroll
    for (int off = 16; off > 0; off >>= 1)
        local += __shfl_down_sync(0xFFFFFFFFu, local, off);

    // ---- cross-CTA: fixed-slot partials + last-block-done gather ----
    unsigned int ticket = 0;
    if (lane == 0) {
        g_partials[bid] = local;
        __threadfence();
        ticket = atomicInc(&g_counter, N_CTAS - 1);   // wraps to 0 after last
    }
    ticket = __shfl_sync(0xFFFFFFFFu, ticket, 0);

    if (ticket == N_CTAS - 1) {      // this CTA is the last to arrive
        __threadfence();
        float s = (lane < N_CTAS) ? ld_volatile(&g_partials[lane]) : 0.0f;
        #pragma unroll
        for (int off = 16; off > 0; off >>= 1)
            s += __shfl_down_sync(0xFFFFFFFFu, s, off);
        if (lane == 0) out[0] = s;
    }
}

extern "C" void kernel_launch(void* const* d_in, const int* in_sizes, int n_in,
                              void* d_out, int out_size) {
    const float* pred  = (const float*)d_in[0];
    const float* label = (const float*)d_in[1];
    float* out = (float*)d_out;
    yolo_loss_kernel<<<N_CTAS, 32>>>(pred, label, out);
}